// round 16
// baseline (speedup 1.0000x reference)
#include <cuda_runtime.h>
#include <cuda_fp16.h>

// Trilinear interpolation, fused repack+interp with per-batch flags:
//   Blocks 0..1007:  repack slabs (batch-major order). Release via
//                    __threadfence + atomicAdd on g_done[b].
//   Blocks 1008+ :   interp (R9 structure: 4 pts/thread, 4 cp.async.cg in one
//                    commit group). Each block loads xnew + computes indices
//                    FIRST, then acquire-spins on g_done[batch] >= 126, then
//                    gathers. cp.async.cg bypasses L1 -> no staleness.
//   Pipeline: batch-0 table ready in ~1-2us; interp overlaps remaining repack.
//   g_done zeroed by a tiny kernel each launch (graph replays).

#define VOL    262144        // 64^3
#define MTOT   884736        // 96^3
#define NC1    63
#define NC3    250047        // 63^3
#define NCELLS (8 * NC3)     // 2,000,376

#define REPACK_BLOCKS 1008   // 8 batches * 126 slabs (63 i-values * 2 halves)
#define INTERP_BLOCKS 6912   // 1,769,472 threads / 256
#define BLOCKS_PER_BATCH 864 // interp blocks per batch
#define SLABS_PER_BATCH 126

__device__ uint4 g_tab[NCELLS];     // 32 MB cell table
__device__ int   g_done[8];         // per-batch repack completion counters

__global__ void zero_flags_kernel()
{
    if (threadIdx.x < 8) g_done[threadIdx.x] = 0;
}

__device__ __forceinline__ unsigned pack2(float a, float b) {
    __half2 h = __floats2half2_rn(a, b);
    return *reinterpret_cast<unsigned*>(&h);
}

__device__ __forceinline__ float lerp1(float a, float b, float t) {
    return fmaf(t, b - a, a);
}

__device__ __forceinline__ float2 h2f(unsigned u) {
    __half2 h = *reinterpret_cast<__half2*>(&u);
    return __half22float2(h);
}

__device__ __forceinline__ unsigned smem_u32(const void* p) {
    return (unsigned)__cvta_generic_to_shared(p);
}

__global__ void __launch_bounds__(256, 8) fused_kernel(
    const float* __restrict__ y,
    const float* __restrict__ xn,
    float* __restrict__ out)
{
    __shared__ __align__(16) char smem_raw[16896];   // max(repack 16896, interp 16384)

    int bid = blockIdx.x;
    int tid = threadIdx.x;

    if (bid < REPACK_BLOCKS) {
        // ---------------- repack path ----------------
        float (*pl)[33 * 64] = reinterpret_cast<float (*)[33 * 64]>(smem_raw);

        int b   = bid / SLABS_PER_BATCH;       // batch-major: batch 0 first
        int r   = bid - b * SLABS_PER_BATCH;   // 0..125
        int i   = r >> 1;                      // 0..62
        int h   = r & 1;
        int j0  = h * 32;
        int nj  = h ? 31 : 32;

        const float* base0 = y + (size_t)b * VOL + (size_t)i * 4096 + j0 * 64;
        // 33 rows * 64 floats = 528 float4 per plane, coalesced
        for (int v = tid; v < 528; v += 256) {
            reinterpret_cast<float4*>(&pl[0][0])[v] =
                __ldg(reinterpret_cast<const float4*>(base0) + v);
            reinterpret_cast<float4*>(&pl[1][0])[v] =
                __ldg(reinterpret_cast<const float4*>(base0 + 4096) + v);
        }
        __syncthreads();

        uint4* dst = g_tab + ((size_t)b * 63 + i) * 3969 + j0 * 63;
        int ncells = nj * 63;
        for (int v = tid; v < ncells; v += 256) {
            int j = v / 63;
            int k = v - j * 63;
            const float* r0 = &pl[0][j * 64 + k];
            const float* r1 = r0 + 64;
            const float* r2 = &pl[1][j * 64 + k];
            const float* r3 = r2 + 64;
            uint4 cell;
            cell.x = pack2(r0[0], r0[1]);   // v000, v001
            cell.y = pack2(r1[0], r1[1]);   // v010, v011
            cell.z = pack2(r2[0], r2[1]);   // v100, v101
            cell.w = pack2(r3[0], r3[1]);   // v110, v111
            dst[v] = cell;
        }

        // release: table writes visible, then signal
        __syncthreads();
        if (tid == 0) {
            __threadfence();
            atomicAdd(&g_done[b], 1);
        }
        return;
    }

    // ---------------- interp path (R9 structure) ----------------
    uint4* stage = reinterpret_cast<uint4*>(smem_raw);   // stage[p*256 + tid]

    int bi = bid - REPACK_BLOCKS;             // 0..6911
    int t  = bi * 256 + tid;
    int b  = bi / BLOCKS_PER_BATCH;           // batch of this block
    int base = b * NC3;

    // 1) stream reads + index math BEFORE waiting (independent of table)
    const float4* xv = reinterpret_cast<const float4*>(xn) + (size_t)t * 3;
    float4 A = __ldcs(xv + 0);
    float4 B = __ldcs(xv + 1);
    float4 C = __ldcs(xv + 2);
    float c[12] = {A.x, A.y, A.z, A.w,
                   B.x, B.y, B.z, B.w,
                   C.x, C.y, C.z, C.w};

    int   cellix[4];
    float f0[4], f1[4], f2[4];
#pragma unroll
    for (int p = 0; p < 4; p++) {
        float r0 = c[3 * p + 0] * 63.0f;
        float r1 = c[3 * p + 1] * 63.0f;
        float r2 = c[3 * p + 2] * 63.0f;
        int i0 = min((int)r0, 62);
        int i1 = min((int)r1, 62);
        int i2 = min((int)r2, 62);
        f0[p] = r0 - (float)i0;
        f1[p] = r1 - (float)i1;
        f2[p] = r2 - (float)i2;
        cellix[p] = base + (i0 * NC1 + i1) * NC1 + i2;
    }

    // 2) acquire-wait for this batch's table
    if (tid == 0) {
        int v;
        do {
            asm volatile("ld.global.acquire.gpu.b32 %0, [%1];"
                         : "=r"(v) : "l"(&g_done[b]) : "memory");
            if (v < SLABS_PER_BATCH) __nanosleep(128);
        } while (v < SLABS_PER_BATCH);
    }
    __syncthreads();

    // 3) fire 4 gathers (cp.async.cg: L2-direct, no stale L1)
#pragma unroll
    for (int p = 0; p < 4; p++) {
        unsigned saddr = smem_u32(&stage[p * 256 + tid]);
        const uint4* gptr = g_tab + cellix[p];
        asm volatile("cp.async.cg.shared.global [%0], [%1], 16;"
                     :: "r"(saddr), "l"(gptr) : "memory");
    }
    asm volatile("cp.async.commit_group;");
    asm volatile("cp.async.wait_group 0;" ::: "memory");

    // 4) lerp trees
    float4 res;
    float* rp = &res.x;
#pragma unroll
    for (int p = 0; p < 4; p++) {
        uint4 q = stage[p * 256 + tid];
        float2 e0 = h2f(q.x);
        float2 e1 = h2f(q.y);
        float2 e2 = h2f(q.z);
        float2 e3 = h2f(q.w);
        float v00 = lerp1(e0.x, e0.y, f2[p]);
        float v01 = lerp1(e1.x, e1.y, f2[p]);
        float v10 = lerp1(e2.x, e2.y, f2[p]);
        float v11 = lerp1(e3.x, e3.y, f2[p]);
        float v0  = lerp1(v00, v01, f1[p]);
        float v1  = lerp1(v10, v11, f1[p]);
        rp[p]     = lerp1(v0, v1, f0[p]);
    }

    __stcs(reinterpret_cast<float4*>(out) + t, res);
}

extern "C" void kernel_launch(void* const* d_in, const int* in_sizes, int n_in,
                              void* d_out, int out_size)
{
    const float* y  = (const float*)d_in[0];   // (8, 64,64,64)
    const float* xn = (const float*)d_in[1];   // (8, 96^3, 3)
    float* out      = (float*)d_out;           // (8, 96^3)

    zero_flags_kernel<<<1, 32>>>();
    fused_kernel<<<REPACK_BLOCKS + INTERP_BLOCKS, 256>>>(y, xn, out);
}